// round 12
// baseline (speedup 1.0000x reference)
#include <cuda_runtime.h>
#include <cuda_fp16.h>
#include <cuda_bf16.h>

// Problem constants (fixed by the dataset)
#define HID    32
#define NIRR   16
#define OUTC   32
#define FANIN  (HID * NIRR)      // 512
#define MAX_ATOMS 50000
#define MAX_EDGES 800000
#define SCAN_BLK 256
#define MAX_SCAN_BLOCKS 512

// agg[t][h*16+i] = sum_{e: tgt=t} nf[src_e][h] * Y[e][i], fp16
__device__ __half g_agg[(size_t)MAX_ATOMS * FANIN];

// Counting-sort scratch (by target). g_count relies on static zero-init for
// the first call; accumulate_kernel re-zeroes it at the end of EVERY call so
// each graph replay (and the correctness call) starts from zeros.
__device__ int    g_count[MAX_ATOMS];
__device__ int    g_offset[MAX_ATOMS];       // destructive cursor
__device__ int    g_rowptr[MAX_ATOMS + 1];   // pristine CSR offsets
__device__ int    g_bsum[MAX_SCAN_BLOCKS];
__device__ int    g_boff[MAX_SCAN_BLOCKS];

// Sorted edge records: Y (16 fp16 = 32 B) + src
__device__ __half g_Yh[(size_t)MAX_EDGES * NIRR];
__device__ int    g_src[MAX_EDGES];

// ---------------------------------------------------------------------------
// Kernel 1: histogram over edge TARGETS. 4 edges/thread via int4 when
// n_edges is a multiple of 4 (keeps the second-row int4 loads 16B-aligned).
// ---------------------------------------------------------------------------
__global__ void hist_kernel(const int* __restrict__ eidx,
                            int n_edges, int n_atoms) {
    int i = blockIdx.x * blockDim.x + threadIdx.x;
    if ((n_edges & 3) == 0) {
        int base = i * 4;
        if (base >= n_edges) return;
        int4 s  = __ldg((const int4*)&eidx[base]);
        int4 tg = __ldg((const int4*)&eidx[n_edges + base]);
        if ((unsigned)s.x < (unsigned)n_atoms && (unsigned)tg.x < (unsigned)n_atoms)
            atomicAdd(&g_count[tg.x], 1);
        if ((unsigned)s.y < (unsigned)n_atoms && (unsigned)tg.y < (unsigned)n_atoms)
            atomicAdd(&g_count[tg.y], 1);
        if ((unsigned)s.z < (unsigned)n_atoms && (unsigned)tg.z < (unsigned)n_atoms)
            atomicAdd(&g_count[tg.z], 1);
        if ((unsigned)s.w < (unsigned)n_atoms && (unsigned)tg.w < (unsigned)n_atoms)
            atomicAdd(&g_count[tg.w], 1);
    } else {
        for (int e = i * 4; e < min(i * 4 + 4, n_edges); e++) {
            int src = eidx[e];
            int tgt = eidx[n_edges + e];
            if ((unsigned)src < (unsigned)n_atoms && (unsigned)tgt < (unsigned)n_atoms)
                atomicAdd(&g_count[tgt], 1);
        }
    }
}

// ---------------------------------------------------------------------------
// Block-local exclusive scan helper (256 threads).
// ---------------------------------------------------------------------------
__device__ __forceinline__ int block_excl_scan_256(int v, int* total) {
    __shared__ int wsum[8];
    __shared__ int tot_s;
    const int tid  = threadIdx.x;
    const int lane = tid & 31;
    const int wid  = tid >> 5;
    int x = v;
#pragma unroll
    for (int d = 1; d < 32; d <<= 1) {
        int t = __shfl_up_sync(0xFFFFFFFFu, x, d);
        if (lane >= d) x += t;
    }
    if (lane == 31) wsum[wid] = x;
    __syncthreads();
    if (tid < 8) {
        int s = wsum[tid];
        int y = s;
#pragma unroll
        for (int d = 1; d < 8; d <<= 1) {
            int t = __shfl_up_sync(0xFFu, y, d);
            if (tid >= d) y += t;
        }
        wsum[tid] = y - s;
    }
    __syncthreads();
    int excl = (x - v) + wsum[wid];
    if (tid == 255) tot_s = excl + v;
    __syncthreads();
    *total = tot_s;
    return excl;
}

__global__ void __launch_bounds__(SCAN_BLK)
scan1_kernel(int n_atoms) {
    int i = blockIdx.x * SCAN_BLK + threadIdx.x;
    int v = (i < n_atoms) ? g_count[i] : 0;
    int total;
    int excl = block_excl_scan_256(v, &total);
    if (i < n_atoms) g_rowptr[i] = excl;
    if (threadIdx.x == 0) g_bsum[blockIdx.x] = total;
}

__global__ void __launch_bounds__(SCAN_BLK)
scan2_kernel(int nblocks, int n_atoms) {
    int v = (threadIdx.x < nblocks) ? g_bsum[threadIdx.x] : 0;
    int total;
    int excl = block_excl_scan_256(v, &total);
    if (threadIdx.x < nblocks) g_boff[threadIdx.x] = excl;
    if (threadIdx.x == 0) g_rowptr[n_atoms] = total;
}

__global__ void __launch_bounds__(SCAN_BLK)
scan3_kernel(int n_atoms) {
    int i = blockIdx.x * SCAN_BLK + threadIdx.x;
    if (i < n_atoms) {
        int r = g_rowptr[i] + g_boff[blockIdx.x];
        g_rowptr[i] = r;
        g_offset[i] = r;
    }
}

// ---------------------------------------------------------------------------
// Kernel 4: scatter edges (sorted by tgt) + precompute Y in fp16.
// ---------------------------------------------------------------------------
__global__ void scatter_kernel(const float* __restrict__ ev,
                               const int* __restrict__ eidx,
                               int n_edges, int n_atoms) {
    int e = blockIdx.x * blockDim.x + threadIdx.x;
    if (e >= n_edges) return;
    int src = eidx[e];
    int tgt = eidx[n_edges + e];
    if ((unsigned)src >= (unsigned)n_atoms || (unsigned)tgt >= (unsigned)n_atoms)
        return;
    int pos = atomicAdd(&g_offset[tgt], 1);

    float ex = __ldg(&ev[(size_t)e * 3 + 0]);
    float ey = __ldg(&ev[(size_t)e * 3 + 1]);
    float ez = __ldg(&ev[(size_t)e * 3 + 2]);
    float r = sqrtf(ex * ex + ey * ey + ez * ez);
    float inv = 1.0f / fmaxf(r, 1e-12f);
    float x = ex * inv, y = ey * inv, z = ez * inv;
    float x2 = x * x, y2 = y * y, z2 = z * z;

    float Y[NIRR];
    Y[0]  = 0.28209479177387814f;
    Y[1]  = 0.4886025119029199f * y;
    Y[2]  = 0.4886025119029199f * z;
    Y[3]  = 0.4886025119029199f * x;
    Y[4]  = 1.0925484305920792f * x * y;
    Y[5]  = 1.0925484305920792f * y * z;
    Y[6]  = 0.31539156525252005f * (3.0f * z2 - 1.0f);
    Y[7]  = 1.0925484305920792f * x * z;
    Y[8]  = 0.5462742152960396f * (x2 - y2);
    Y[9]  = 0.5900435899266435f * y * (3.0f * x2 - y2);
    Y[10] = 2.890611442640554f  * x * y * z;
    Y[11] = 0.4570457994644658f * y * (5.0f * z2 - 1.0f);
    Y[12] = 0.3731763325901154f * z * (5.0f * z2 - 3.0f);
    Y[13] = 0.4570457994644658f * x * (5.0f * z2 - 1.0f);
    Y[14] = 1.445305721320277f  * z * (x2 - y2);
    Y[15] = 0.5900435899266435f * x * (x2 - 3.0f * y2);

    __half2 yh[8];
#pragma unroll
    for (int j = 0; j < 8; j++)
        yh[j] = __floats2half2_rn(Y[2 * j], Y[2 * j + 1]);
    uint4* dst = (uint4*)&g_Yh[(size_t)pos * NIRR];
    dst[0] = *(uint4*)&yh[0];
    dst[1] = *(uint4*)&yh[4];
    g_src[pos] = src;
}

// ---------------------------------------------------------------------------
// Kernel 5: accumulate. One warp per TARGET atom, lane = hidden channel h.
// 4-edge software pipeline: batch the (src, Y) loads, then 4 independent nf
// gathers (MLP=4), then FMAs. Re-zeroes g_count for the next replay.
// ---------------------------------------------------------------------------
__global__ void __launch_bounds__(256)
accumulate_kernel(const float* __restrict__ nf, int n_atoms) {
    const int warp_g = (blockIdx.x * blockDim.x + threadIdx.x) >> 5;
    if (warp_g >= n_atoms) return;
    const int t = warp_g;
    const int lane = threadIdx.x & 31;

    if (lane == 0) g_count[t] = 0;   // reset histogram for next call/replay

    const int rs = __ldg(&g_rowptr[t]);
    const int re = __ldg(&g_rowptr[t + 1]);

    float M[NIRR];
#pragma unroll
    for (int i = 0; i < NIRR; i++) M[i] = 0.f;

    for (int base = rs; base < re; base += 4) {
        int   srcs[4];
        uint4 ya[4], yb[4];
#pragma unroll
        for (int j = 0; j < 4; j++) {
            int e = (base + j < re) ? (base + j) : base;   // clamp (masked later)
            srcs[j] = __ldg(&g_src[e]);
            ya[j]   = __ldg((const uint4*)&g_Yh[(size_t)e * NIRR]);
            yb[j]   = __ldg((const uint4*)&g_Yh[(size_t)e * NIRR + 8]);
        }
        float nfv[4];
#pragma unroll
        for (int j = 0; j < 4; j++)
            nfv[j] = __ldg(&nf[(size_t)srcs[j] * HID + lane]);

#pragma unroll
        for (int j = 0; j < 4; j++) {
            if (base + j < re) {
                const __half2* ha = (const __half2*)&ya[j];
                const __half2* hb = (const __half2*)&yb[j];
                const float v = nfv[j];
#pragma unroll
                for (int q = 0; q < 4; q++) {
                    float2 f = __half22float2(ha[q]);
                    M[2 * q]     = fmaf(v, f.x, M[2 * q]);
                    M[2 * q + 1] = fmaf(v, f.y, M[2 * q + 1]);
                }
#pragma unroll
                for (int q = 0; q < 4; q++) {
                    float2 f = __half22float2(hb[q]);
                    M[8 + 2 * q]     = fmaf(v, f.x, M[8 + 2 * q]);
                    M[8 + 2 * q + 1] = fmaf(v, f.y, M[8 + 2 * q + 1]);
                }
            }
        }
    }

    // agg[t][lane*16 + i] as fp16: 32 B per lane, coalesced 1 KB/warp.
    __half2 mh[8];
#pragma unroll
    for (int j = 0; j < 8; j++)
        mh[j] = __floats2half2_rn(M[2 * j], M[2 * j + 1]);
    uint4* dst = (uint4*)&g_agg[(size_t)t * FANIN + lane * NIRR];
    dst[0] = *(uint4*)&mh[0];
    dst[1] = *(uint4*)&mh[4];
}

// ---------------------------------------------------------------------------
// Kernel 6: out = agg @ W + b  via mma.sync m16n8k16 (fp16 in, f32 accum).
// Block = 128 threads (4 warps), M-tile 64 rows, K = 512 in 4 chunks of 128.
// ---------------------------------------------------------------------------
#define GE_BM 64
#define SA_STRIDE 136
#define SWG_STRIDE 40

__global__ void __launch_bounds__(128)
gemm_out_kernel(const float* __restrict__ W,
                const float* __restrict__ bias,
                float* __restrict__ out, int n_atoms) {
    __shared__ __half sA[GE_BM * SA_STRIDE];   // 17,408 B
    __shared__ __half sW[128 * SWG_STRIDE];    // 10,240 B

    const int tid  = threadIdx.x;
    const int warp = tid >> 5;
    const int lane = tid & 31;
    const int m_base = blockIdx.x * GE_BM;

    float c[4][4];
#pragma unroll
    for (int t = 0; t < 4; t++) {
        c[t][0] = 0.f; c[t][1] = 0.f; c[t][2] = 0.f; c[t][3] = 0.f;
    }

    const uint4 zero4 = make_uint4(0, 0, 0, 0);
    const float4* __restrict__ W4 = (const float4*)W;

    for (int kc = 0; kc < 4; kc++) {
        for (int i = tid; i < 1024; i += 128) {
            int r = i >> 4, c8 = i & 15;
            int a = m_base + r;
            uint4 val = (a < n_atoms)
                ? __ldg((const uint4*)&g_agg[(size_t)a * FANIN + kc * 128 + c8 * 8])
                : zero4;
            *(uint4*)&sA[r * SA_STRIDE + c8 * 8] = val;
        }
        for (int i = tid; i < 1024; i += 128) {
            int r = i >> 3, q = i & 7;
            float4 w = __ldg(&W4[(size_t)(kc * 128 + r) * 8 + q]);
            *(__half2*)&sW[r * SWG_STRIDE + q * 4]     = __floats2half2_rn(w.x, w.y);
            *(__half2*)&sW[r * SWG_STRIDE + q * 4 + 2] = __floats2half2_rn(w.z, w.w);
        }
        __syncthreads();

#pragma unroll
        for (int ks2 = 0; ks2 < 4; ks2++) {
            unsigned a0[4], a1[4];
            {
                int row = warp * 16 + (lane & 15);
                int colh = (lane >> 4) * 8;
                unsigned addr0 = (unsigned)__cvta_generic_to_shared(
                    &sA[row * SA_STRIDE + ks2 * 32 + colh]);
                unsigned addr1 = (unsigned)__cvta_generic_to_shared(
                    &sA[row * SA_STRIDE + ks2 * 32 + 16 + colh]);
                asm volatile(
                    "ldmatrix.sync.aligned.m8n8.x4.shared.b16 {%0,%1,%2,%3}, [%4];"
                    : "=r"(a0[0]), "=r"(a0[1]), "=r"(a0[2]), "=r"(a0[3])
                    : "r"(addr0));
                asm volatile(
                    "ldmatrix.sync.aligned.m8n8.x4.shared.b16 {%0,%1,%2,%3}, [%4];"
                    : "=r"(a1[0]), "=r"(a1[1]), "=r"(a1[2]), "=r"(a1[3])
                    : "r"(addr1));
            }
#pragma unroll
            for (int t = 0; t < 4; t++) {
                unsigned b[4];
                unsigned addr = (unsigned)__cvta_generic_to_shared(
                    &sW[(ks2 * 32 + lane) * SWG_STRIDE + t * 8]);
                asm volatile(
                    "ldmatrix.sync.aligned.m8n8.x4.trans.shared.b16 {%0,%1,%2,%3}, [%4];"
                    : "=r"(b[0]), "=r"(b[1]), "=r"(b[2]), "=r"(b[3])
                    : "r"(addr));
                asm volatile(
                    "mma.sync.aligned.m16n8k16.row.col.f32.f16.f16.f32 "
                    "{%0,%1,%2,%3}, {%4,%5,%6,%7}, {%8,%9}, {%0,%1,%2,%3};"
                    : "+f"(c[t][0]), "+f"(c[t][1]), "+f"(c[t][2]), "+f"(c[t][3])
                    : "r"(a0[0]), "r"(a0[1]), "r"(a0[2]), "r"(a0[3]),
                      "r"(b[0]), "r"(b[1]));
                asm volatile(
                    "mma.sync.aligned.m16n8k16.row.col.f32.f16.f16.f32 "
                    "{%0,%1,%2,%3}, {%4,%5,%6,%7}, {%8,%9}, {%0,%1,%2,%3};"
                    : "+f"(c[t][0]), "+f"(c[t][1]), "+f"(c[t][2]), "+f"(c[t][3])
                    : "r"(a1[0]), "r"(a1[1]), "r"(a1[2]), "r"(a1[3]),
                      "r"(b[2]), "r"(b[3]));
            }
        }
        __syncthreads();
    }

    const int r0  = lane >> 2;
    const int cb  = (lane & 3) * 2;
    const int ga0 = m_base + warp * 16 + r0;
    const int ga1 = ga0 + 8;
#pragma unroll
    for (int t = 0; t < 4; t++) {
        int col = t * 8 + cb;
        float2 bb = *(const float2*)&bias[col];
        if (ga0 < n_atoms) {
            float2 v = make_float2(c[t][0] + bb.x, c[t][1] + bb.y);
            *(float2*)&out[(size_t)ga0 * OUTC + col] = v;
        }
        if (ga1 < n_atoms) {
            float2 v = make_float2(c[t][2] + bb.x, c[t][3] + bb.y);
            *(float2*)&out[(size_t)ga1 * OUTC + col] = v;
        }
    }
}

// ---------------------------------------------------------------------------
// Launcher
// Inputs (metadata order): node_features f32 [n_atoms,32], edge_vectors f32
// [n_edges,3], edge_index int32 [2,n_edges], W f32 [512,32], b f32 [32].
// Output: f32 [n_atoms, 32].
// ---------------------------------------------------------------------------
extern "C" void kernel_launch(void* const* d_in, const int* in_sizes, int n_in,
                              void* d_out, int out_size) {
    const float* nf  = (const float*)d_in[0];
    const float* ev  = (const float*)d_in[1];
    const int*   ei  = (const int*)d_in[2];
    const float* W   = (const float*)d_in[3];
    const float* b   = (const float*)d_in[4];
    float*       out = (float*)d_out;

    const int n_atoms = in_sizes[0] / HID;
    const int n_edges = in_sizes[1] / 3;
    const int nblocks = (n_atoms + SCAN_BLK - 1) / SCAN_BLK;

    // Counting sort of edges by TARGET -> CSR (g_count zeroed by previous
    // accumulate_kernel call, or static-zero on first call)
    {
        int nthreads = (n_edges + 3) / 4;
        hist_kernel<<<(nthreads + 255) / 256, 256>>>(ei, n_edges, n_atoms);
    }
    scan1_kernel<<<nblocks, SCAN_BLK>>>(n_atoms);
    scan2_kernel<<<1, SCAN_BLK>>>(nblocks, n_atoms);
    scan3_kernel<<<nblocks, SCAN_BLK>>>(n_atoms);
    scatter_kernel<<<(n_edges + 255) / 256, 256>>>(ev, ei, n_edges, n_atoms);

    // agg[t] = sum nf[src] (x) Y  — warp per target, 4-edge pipeline
    {
        int grid = (n_atoms + 7) / 8;
        accumulate_kernel<<<grid, 256>>>(nf, n_atoms);
    }

    // out = agg @ W + b  (tensor cores)
    {
        int grid = (n_atoms + GE_BM - 1) / GE_BM;
        gemm_out_kernel<<<grid, 128>>>(W, b, out, n_atoms);
    }
}

// round 14
// speedup vs baseline: 1.4068x; 1.4068x over previous
#include <cuda_runtime.h>
#include <cuda_fp16.h>
#include <cuda_bf16.h>

// Problem constants (fixed by the dataset)
#define HID    32
#define NIRR   16
#define OUTC   32
#define FANIN  (HID * NIRR)      // 512
#define MAX_ATOMS 50000

// Scratch: A[a][i*32+c] = sum_h nf[a][h] * W[(h*16+i)*32+c], stored fp16.
// Row = 512 halves = 1024 B = 8 x 128B lines. Line l holds irreps 2l, 2l+1.
__device__ __half g_Ah[(size_t)MAX_ATOMS * FANIN];

// ---------------------------------------------------------------------------
// Kernel 1: A = NF @ W'  via mma.sync m16n8k16 (fp16 in, fp32 accum).
// Also initializes out[rows of this tile] = b (replaces a separate init
// kernel; stream order guarantees completion before the edge kernel's REDs).
// Block = 128 threads (4 warps), M-tile = 64 rows, N = 512 in 8 chunks of 64.
//   sW [k=32][n=512] fp16, stride 520 halves (conflict-free ldmatrix.trans)
//   sNF[m=64][k=32]  fp16, stride 40 halves
//   sStage[warp][16 x 72] fp16 epilogue staging (stride 72 -> +4 banks/row)
// Warp w owns rows w*16..w*16+15. A-frags held in regs across all N.
// Epilogue: STS.32 frags -> smem, then coalesced STG.128 to g_Ah.
// ---------------------------------------------------------------------------
#define PRE_BM 64
#define SW_STRIDE 520
#define SNF_STRIDE 40
#define STG_STRIDE 72

__global__ void __launch_bounds__(128)
precompute_mma_kernel(const float* __restrict__ nf,
                      const float* __restrict__ W,
                      const float4* __restrict__ b4,
                      float4* __restrict__ out4,
                      int n_atoms) {
    __shared__ __half sW[HID * SW_STRIDE];        // 33,280 B
    __shared__ __half sNF[PRE_BM * SNF_STRIDE];   //  5,120 B
    __shared__ __half sStage[4][16 * STG_STRIDE]; //  9,216 B

    const int tid  = threadIdx.x;
    const int warp = tid >> 5;
    const int lane = tid & 31;
    const int m_base = blockIdx.x * PRE_BM;

    // Initialize out = b for this tile's rows: 64 rows x 8 float4 = 512 float4.
    {
        for (int i = tid; i < PRE_BM * (OUTC / 4); i += 128) {
            int a = m_base + (i >> 3);
            if (a < n_atoms) out4[(size_t)a * (OUTC / 4) + (i & 7)] = __ldg(&b4[i & 7]);
        }
    }

    // Stage W via float4: 16384 f32 = 4096 float4. flat = (h*16+i)*32+c.
    {
        const float4* __restrict__ W4 = (const float4*)W;
        for (int i = tid; i < 4096; i += 128) {
            float4 w = __ldg(&W4[i]);
            int base = i * 4;
            int h = base >> 9, rem = base & 511;
            *(__half2*)&sW[h * SW_STRIDE + rem]     = __floats2half2_rn(w.x, w.y);
            *(__half2*)&sW[h * SW_STRIDE + rem + 2] = __floats2half2_rn(w.z, w.w);
        }
    }
    // Stage nf tile via float4 (zero-padded beyond n_atoms)
    {
        const float4* __restrict__ nf4 = (const float4*)nf;
        for (int i = tid; i < PRE_BM * HID / 4; i += 128) {   // 512 float4
            int r = i >> 3, q = i & 7;
            int a = m_base + r;
            float4 v = (a < n_atoms) ? __ldg(&nf4[(size_t)a * 8 + q])
                                     : make_float4(0.f, 0.f, 0.f, 0.f);
            *(__half2*)&sNF[r * SNF_STRIDE + q * 4]     = __floats2half2_rn(v.x, v.y);
            *(__half2*)&sNF[r * SNF_STRIDE + q * 4 + 2] = __floats2half2_rn(v.z, v.w);
        }
    }
    __syncthreads();

    // A fragments: m16k16 x 2 k-steps, canonical row-major ldmatrix.x4
    unsigned afrag[2][4];
    {
        int row  = warp * 16 + (lane & 15);
        int colh = (lane >> 4) * 8;
#pragma unroll
        for (int ks = 0; ks < 2; ks++) {
            unsigned addr = (unsigned)__cvta_generic_to_shared(
                &sNF[row * SNF_STRIDE + ks * 16 + colh]);
            asm volatile(
                "ldmatrix.sync.aligned.m8n8.x4.shared.b16 {%0,%1,%2,%3}, [%4];"
                : "=r"(afrag[ks][0]), "=r"(afrag[ks][1]),
                  "=r"(afrag[ks][2]), "=r"(afrag[ks][3])
                : "r"(addr));
        }
    }

    const int r0 = lane >> 2;          // C frag row within m16
    const int cb = (lane & 3) * 2;     // C frag col pair within n8
    __half* __restrict__ st = sStage[warp];

#pragma unroll
    for (int nc = 0; nc < 8; nc++) {
        float c[8][4];
#pragma unroll
        for (int t = 0; t < 8; t++) {
            c[t][0] = 0.f; c[t][1] = 0.f; c[t][2] = 0.f; c[t][3] = 0.f;
        }
#pragma unroll
        for (int t = 0; t < 8; t++) {
            unsigned b[4];
            unsigned addr = (unsigned)__cvta_generic_to_shared(
                &sW[lane * SW_STRIDE + nc * 64 + t * 8]);
            asm volatile(
                "ldmatrix.sync.aligned.m8n8.x4.trans.shared.b16 {%0,%1,%2,%3}, [%4];"
                : "=r"(b[0]), "=r"(b[1]), "=r"(b[2]), "=r"(b[3])
                : "r"(addr));
            asm volatile(
                "mma.sync.aligned.m16n8k16.row.col.f32.f16.f16.f32 "
                "{%0,%1,%2,%3}, {%4,%5,%6,%7}, {%8,%9}, {%0,%1,%2,%3};"
                : "+f"(c[t][0]), "+f"(c[t][1]), "+f"(c[t][2]), "+f"(c[t][3])
                : "r"(afrag[0][0]), "r"(afrag[0][1]),
                  "r"(afrag[0][2]), "r"(afrag[0][3]),
                  "r"(b[0]), "r"(b[1]));
            asm volatile(
                "mma.sync.aligned.m16n8k16.row.col.f32.f16.f16.f32 "
                "{%0,%1,%2,%3}, {%4,%5,%6,%7}, {%8,%9}, {%0,%1,%2,%3};"
                : "+f"(c[t][0]), "+f"(c[t][1]), "+f"(c[t][2]), "+f"(c[t][3])
                : "r"(afrag[1][0]), "r"(afrag[1][1]),
                  "r"(afrag[1][2]), "r"(afrag[1][3]),
                  "r"(b[2]), "r"(b[3]));
        }
        // Stage C tile (16 x 64 halves) into padded smem
#pragma unroll
        for (int t = 0; t < 8; t++) {
            *(__half2*)&st[r0 * STG_STRIDE + t * 8 + cb] =
                __floats2half2_rn(c[t][0], c[t][1]);
            *(__half2*)&st[(r0 + 8) * STG_STRIDE + t * 8 + cb] =
                __floats2half2_rn(c[t][2], c[t][3]);
        }
        __syncwarp();
        // Coalesced copy-out: 128 uint4 (16 rows x 8 uint4) per warp tile
#pragma unroll
        for (int j = 0; j < 4; j++) {
            int idx = j * 32 + lane;
            int row = idx >> 3, col = idx & 7;
            uint4 val = *(uint4*)&st[row * STG_STRIDE + col * 8];
            int ga = m_base + warp * 16 + row;
            if (ga < n_atoms)
                *(uint4*)&g_Ah[(size_t)ga * FANIN + nc * 64 + col * 8] = val;
        }
        __syncwarp();
    }
}

// ---------------------------------------------------------------------------
// Kernel 2: per-edge contribution. 4 edges per warp, 8 lanes per edge.
//   sub = lane>>3 : edge slot;  el = lane&7 : lane within edge group
// 8 x LDG.128 per lane; lane el's uint4 at line l covers irrep 2l+(el>>2),
// channels (el&3)*8..+7. shfl_xor(4) folds irrep parity; each lane REDs
// 4 channels with one red.global.add.v4.f32.
// ---------------------------------------------------------------------------
__global__ void __launch_bounds__(256)
edge_kernel(const float* __restrict__ ev,
            const int* __restrict__ eidx,
            float* __restrict__ out,
            int n_edges, int n_atoms) {
    const int lane  = threadIdx.x & 31;
    const int gwarp = (blockIdx.x * blockDim.x + threadIdx.x) >> 5;
    const int sub   = lane >> 3;
    const int el    = lane & 7;
    const int e     = gwarp * 4 + sub;
    if (e >= n_edges) return;                    // 8-lane group exits together

    const unsigned gmask = 0xFFu << (sub * 8);

    const int src = eidx[e];
    const int tgt = eidx[n_edges + e];
    if ((unsigned)src >= (unsigned)n_atoms || (unsigned)tgt >= (unsigned)n_atoms)
        return;

    const float ex = __ldg(&ev[(size_t)e * 3 + 0]);
    const float ey = __ldg(&ev[(size_t)e * 3 + 1]);
    const float ez = __ldg(&ev[(size_t)e * 3 + 2]);

    float r = sqrtf(ex * ex + ey * ey + ez * ez);
    float inv = 1.0f / fmaxf(r, 1e-12f);
    float x = ex * inv, y = ey * inv, z = ez * inv;
    float x2 = x * x, y2 = y * y, z2 = z * z;

    float Y[NIRR];
    Y[0]  = 0.28209479177387814f;
    Y[1]  = 0.4886025119029199f * y;
    Y[2]  = 0.4886025119029199f * z;
    Y[3]  = 0.4886025119029199f * x;
    Y[4]  = 1.0925484305920792f * x * y;
    Y[5]  = 1.0925484305920792f * y * z;
    Y[6]  = 0.31539156525252005f * (3.0f * z2 - 1.0f);
    Y[7]  = 1.0925484305920792f * x * z;
    Y[8]  = 0.5462742152960396f * (x2 - y2);
    Y[9]  = 0.5900435899266435f * y * (3.0f * x2 - y2);
    Y[10] = 2.890611442640554f  * x * y * z;
    Y[11] = 0.4570457994644658f * y * (5.0f * z2 - 1.0f);
    Y[12] = 0.3731763325901154f * z * (5.0f * z2 - 3.0f);
    Y[13] = 0.4570457994644658f * x * (5.0f * z2 - 1.0f);
    Y[14] = 1.445305721320277f  * z * (x2 - y2);
    Y[15] = 0.5900435899266435f * x * (x2 - 3.0f * y2);

    const uint4* __restrict__ Arow4 =
        (const uint4*)(g_Ah + (size_t)src * FANIN);
    uint4 v[8];
#pragma unroll
    for (int l = 0; l < 8; l++)
        v[l] = __ldg(&Arow4[l * 8 + el]);

    const int par = el >> 2;

    float acc[8];
#pragma unroll
    for (int i = 0; i < 8; i++) acc[i] = 0.f;

#pragma unroll
    for (int l = 0; l < 8; l++) {
        float yi = par ? Y[2 * l + 1] : Y[2 * l];
        float2 f0 = __half22float2(*(const __half2*)&v[l].x);
        float2 f1 = __half22float2(*(const __half2*)&v[l].y);
        float2 f2 = __half22float2(*(const __half2*)&v[l].z);
        float2 f3 = __half22float2(*(const __half2*)&v[l].w);
        acc[0] = fmaf(yi, f0.x, acc[0]); acc[1] = fmaf(yi, f0.y, acc[1]);
        acc[2] = fmaf(yi, f1.x, acc[2]); acc[3] = fmaf(yi, f1.y, acc[3]);
        acc[4] = fmaf(yi, f2.x, acc[4]); acc[5] = fmaf(yi, f2.y, acc[5]);
        acc[6] = fmaf(yi, f3.x, acc[6]); acc[7] = fmaf(yi, f3.y, acc[7]);
    }

#pragma unroll
    for (int i = 0; i < 8; i++)
        acc[i] += __shfl_xor_sync(gmask, acc[i], 4);

    float r0 = par ? acc[4] : acc[0];
    float r1 = par ? acc[5] : acc[1];
    float r2 = par ? acc[6] : acc[2];
    float r3 = par ? acc[7] : acc[3];

    float* dst = &out[(size_t)tgt * OUTC + (el & 3) * 8 + par * 4];
    asm volatile("red.global.add.v4.f32 [%0], {%1, %2, %3, %4};"
                 :: "l"(dst), "f"(r0), "f"(r1), "f"(r2), "f"(r3)
                 : "memory");
}

// ---------------------------------------------------------------------------
// Launcher
// Inputs (metadata order): node_features f32 [n_atoms,32], edge_vectors f32
// [n_edges,3], edge_index int32 [2,n_edges], W f32 [512,32], b f32 [32].
// Output: f32 [n_atoms, 32].
// ---------------------------------------------------------------------------
extern "C" void kernel_launch(void* const* d_in, const int* in_sizes, int n_in,
                              void* d_out, int out_size) {
    const float* nf  = (const float*)d_in[0];
    const float* ev  = (const float*)d_in[1];
    const int*   ei  = (const int*)d_in[2];
    const float* W   = (const float*)d_in[3];
    const float* b   = (const float*)d_in[4];
    float*       out = (float*)d_out;

    const int n_atoms = in_sizes[0] / HID;
    const int n_edges = in_sizes[1] / 3;

    // A = NF @ W' via tensor cores; also writes out = b for its rows.
    {
        int grid = (n_atoms + PRE_BM - 1) / PRE_BM;
        precompute_mma_kernel<<<grid, 128>>>(nf, W, (const float4*)b,
                                             (float4*)out, n_atoms);
    }

    // per-edge gather + scatter: 4 edges/warp, 32 edges/block
    {
        int grid = (n_edges + 31) / 32;
        edge_kernel<<<grid, 256>>>(ev, ei, out, n_edges, n_atoms);
    }
}